// round 10
// baseline (speedup 1.0000x reference)
#include <cuda_runtime.h>
#include <cuda_bf16.h>
#include <stdint.h>

#define NTOK   16384
#define DIM    256
#define NCODES 8192
#define BM     128
#define BN     64
#define XSTR   36

// Device-global scratch. CRITICAL: only ever referenced from DEVICE code.
// (Passing these as kernel args from host passes the host shadow address,
// which GB300's ATS happily dereferences into host memory — silent garbage.)
__device__ unsigned long long g_key[NTOK];
__device__ float  g_rown[NTOK];
__device__ float  g_coden[NCODES];
__device__ double g_partial[256];

// ---------------------------------------------------------------------------
__global__ void k_init(void) {
    int n = blockIdx.x * 256 + threadIdx.x;
    if (n < NTOK) g_key[n] = ~0ull;
}

// ---------------------------------------------------------------------------
// Squared L2 norms, one warp per row; writes the device symbols directly.
__global__ void k_norm(const float* __restrict__ src, int nrows, int which) {
    int gwarp = (blockIdx.x * blockDim.x + threadIdx.x) >> 5;
    int lane  = threadIdx.x & 31;
    if (gwarp >= nrows) return;
    const float4* s4 = reinterpret_cast<const float4*>(src) + (size_t)gwarp * 64;
    float a = 0.0f;
#pragma unroll
    for (int it = 0; it < 2; it++) {
        float4 v = s4[it * 32 + lane];
        a = __fadd_rn(a, __fmul_rn(v.x, v.x));
        a = __fadd_rn(a, __fmul_rn(v.y, v.y));
        a = __fadd_rn(a, __fmul_rn(v.z, v.z));
        a = __fadd_rn(a, __fmul_rn(v.w, v.w));
    }
#pragma unroll
    for (int off = 16; off >= 1; off >>= 1)
        a += __shfl_xor_sync(0xffffffffu, a, off);
    if (lane == 0) {
        if (which == 0) g_rown[gwarp]  = a;
        else            g_coden[gwarp] = a;
    }
}

// ---------------------------------------------------------------------------
// Fused fp32 GEMM + argmin. Block = 128 rows x 64 codes, d chunked by 32.
// dist = fsub(fadd(rown, coden), 2*dot); key = (dist_bits<<32)|k gives
// first-index tie-break (all dists positive here, so bit-compare is ordered).
__global__ void __launch_bounds__(256, 2)
k_main(const float* __restrict__ x, const float* __restrict__ cb) {
    __shared__ float xs[BM * XSTR];
    __shared__ float es[BN * XSTR];
    const int tid = threadIdx.x;
    const int tx  = tid & 15;
    const int ty  = tid >> 4;
    const int rowbase = blockIdx.x * BM;
    const int kbase   = blockIdx.y * BN;
    const float4* x4  = reinterpret_cast<const float4*>(x);
    const float4* cb4 = reinterpret_cast<const float4*>(cb);

    float acc[8][4];
#pragma unroll
    for (int i = 0; i < 8; i++)
#pragma unroll
        for (int j = 0; j < 4; j++) acc[i][j] = 0.0f;

#pragma unroll 1
    for (int t = 0; t < DIM / 32; t++) {
        __syncthreads();
#pragma unroll
        for (int it = 0; it < 4; it++) {
            int i = it * 256 + tid, r = i >> 3, d4 = i & 7;
            *reinterpret_cast<float4*>(&xs[r * XSTR + d4 * 4]) =
                x4[(size_t)(rowbase + r) * 64 + t * 8 + d4];
        }
#pragma unroll
        for (int it = 0; it < 2; it++) {
            int i = it * 256 + tid, k = i >> 3, d4 = i & 7;
            *reinterpret_cast<float4*>(&es[k * XSTR + d4 * 4]) =
                cb4[(size_t)(kbase + k) * 64 + t * 8 + d4];
        }
        __syncthreads();
#pragma unroll
        for (int d4 = 0; d4 < 8; d4++) {
            float4 xv[8], ev[4];
#pragma unroll
            for (int i = 0; i < 8; i++)
                xv[i] = *reinterpret_cast<const float4*>(&xs[(i * 16 + ty) * XSTR + d4 * 4]);
#pragma unroll
            for (int j = 0; j < 4; j++)
                ev[j] = *reinterpret_cast<const float4*>(&es[(j * 16 + tx) * XSTR + d4 * 4]);
#pragma unroll
            for (int i = 0; i < 8; i++)
#pragma unroll
                for (int j = 0; j < 4; j++) {
                    acc[i][j] = __fmaf_rn(xv[i].x, ev[j].x, acc[i][j]);
                    acc[i][j] = __fmaf_rn(xv[i].y, ev[j].y, acc[i][j]);
                    acc[i][j] = __fmaf_rn(xv[i].z, ev[j].z, acc[i][j]);
                    acc[i][j] = __fmaf_rn(xv[i].w, ev[j].w, acc[i][j]);
                }
        }
    }

    float rr[8];
#pragma unroll
    for (int i = 0; i < 8; i++) rr[i] = g_rown[rowbase + i * 16 + ty];
    unsigned long long bk[8];
#pragma unroll
    for (int i = 0; i < 8; i++) bk[i] = ~0ull;
#pragma unroll
    for (int j = 0; j < 4; j++) {
        int   kg = kbase + j * 16 + tx;
        float c  = g_coden[kg];
#pragma unroll
        for (int i = 0; i < 8; i++) {
            float dist = __fsub_rn(__fadd_rn(rr[i], c), 2.0f * acc[i][j]);
            unsigned long long key =
                ((unsigned long long)__float_as_uint(dist) << 32) | (unsigned)kg;
            if (key < bk[i]) bk[i] = key;
        }
    }
#pragma unroll
    for (int i = 0; i < 8; i++) {
        unsigned long long k = bk[i];
#pragma unroll
        for (int off = 8; off >= 1; off >>= 1) {
            unsigned long long o = __shfl_xor_sync(0xffffffffu, k, off);
            if (o < k) k = o;
        }
        if (tx == 0) atomicMin(&g_key[rowbase + i * 16 + ty], k);
    }
}

// ---------------------------------------------------------------------------
// Gather + straight-through roundings + loss partials (double).
__global__ void k_gather(const float* __restrict__ x, const float* __restrict__ cb,
                         float* __restrict__ out, int out_size) {
    double ls = 0.0;
    const int total = NTOK * DIM;
    for (int e = blockIdx.x * 256 + threadIdx.x; e < total; e += 256 * 256) {
        int n = e >> 8, d = e & 255;
        int idx = (int)(unsigned)(g_key[n] & 0xffffffffull);
        float q  = __ldg(&cb[idx * DIM + d]);
        float xv = x[e];
        float diff = __fsub_rn(q, xv);
        if (e < out_size) out[e] = __fadd_rn(xv, diff);
        ls += (double)__fmul_rn(diff, diff);
    }
#pragma unroll
    for (int off = 16; off >= 1; off >>= 1)
        ls += __shfl_xor_sync(0xffffffffu, ls, off);
    __shared__ double ws[8];
    if ((threadIdx.x & 31) == 0) ws[threadIdx.x >> 5] = ls;
    __syncthreads();
    if (threadIdx.x == 0) {
        double t = 0.0;
        for (int w = 0; w < 8; w++) t += ws[w];
        g_partial[blockIdx.x] = t;
    }
}

// ---------------------------------------------------------------------------
__global__ void k_finalize(float* __restrict__ out, int out_size) {
    if (blockIdx.x < 64) {
        int n = blockIdx.x * 256 + threadIdx.x;
        int pos = NTOK * DIM + n;
        if (pos < out_size)
            out[pos] = (float)(unsigned)(g_key[n] & 0xffffffffull);
    } else if (threadIdx.x == 0) {
        double s = 0.0;
        for (int b = 0; b < 256; b++) s += g_partial[b];
        int pos = NTOK * DIM + NTOK;
        if (pos < out_size)
            out[pos] = 0.25f * (float)(s / (double)(NTOK * DIM));
    }
}

// ---------------------------------------------------------------------------
extern "C" void kernel_launch(void* const* d_in, const int* in_sizes, int n_in,
                              void* d_out, int out_size) {
    const float* x  = (const float*)d_in[0];
    const float* cb = (const float*)d_in[1];
    if (n_in >= 2 && in_sizes[0] == NCODES * DIM) {
        cb = (const float*)d_in[0];
        x  = (const float*)d_in[1];
    }
    float* out = (float*)d_out;

    k_init<<<(NTOK + 255) / 256, 256>>>();
    k_norm<<<NTOK / 8, 256>>>(x, NTOK, 0);
    k_norm<<<NCODES / 8, 256>>>(cb, NCODES, 1);
    k_main<<<dim3(NTOK / BM, NCODES / BN), 256>>>(x, cb);
    k_gather<<<256, 256>>>(x, cb, out, out_size);
    k_finalize<<<65, 256>>>(out, out_size);
}

// round 11
// speedup vs baseline: 1.1177x; 1.1177x over previous
#include <cuda_runtime.h>
#include <cuda_bf16.h>
#include <stdint.h>

#define NTOK   16384
#define DIM    256
#define NCODES 8192
#define BM     128
#define BN     128
#define BK     32
#define XSTR   36                // 32-float chunk row + 4 pad
#define TILE   (128 * XSTR)      // floats per stage per matrix

// Device-global scratch. Only referenced from DEVICE code (GB300 ATS trap:
// passing __device__ symbols as kernel args dereferences host memory).
__device__ unsigned long long g_key[NTOK];
__device__ float  g_rown[NTOK];
__device__ float  g_coden[NCODES];
__device__ double g_partial[1024];

// ---------------------------------------------------------------------------
__global__ void k_init(void) {
    int n = blockIdx.x * 256 + threadIdx.x;
    if (n < NTOK) g_key[n] = ~0ull;
}

// ---------------------------------------------------------------------------
__global__ void k_norm(const float* __restrict__ src, int nrows, int which) {
    int gwarp = (blockIdx.x * blockDim.x + threadIdx.x) >> 5;
    int lane  = threadIdx.x & 31;
    if (gwarp >= nrows) return;
    const float4* s4 = reinterpret_cast<const float4*>(src) + (size_t)gwarp * 64;
    float a = 0.0f;
#pragma unroll
    for (int it = 0; it < 2; it++) {
        float4 v = s4[it * 32 + lane];
        a = __fadd_rn(a, __fmul_rn(v.x, v.x));
        a = __fadd_rn(a, __fmul_rn(v.y, v.y));
        a = __fadd_rn(a, __fmul_rn(v.z, v.z));
        a = __fadd_rn(a, __fmul_rn(v.w, v.w));
    }
#pragma unroll
    for (int off = 16; off >= 1; off >>= 1)
        a += __shfl_xor_sync(0xffffffffu, a, off);
    if (lane == 0) {
        if (which == 0) g_rown[gwarp]  = a;
        else            g_coden[gwarp] = a;
    }
}

// ---------------------------------------------------------------------------
// Fused fp32 GEMM + argmin. Block = 128 rows x 128 codes, 8x8 micro-tile,
// double-buffered smem (BK=32 chunks), one __syncthreads per chunk.
// dist = fsub(fadd(rown, coden), 2*dot); key=(dist_bits<<32)|k (first-index ties).
__global__ void __launch_bounds__(256, 1)
k_main(const float* __restrict__ x, const float* __restrict__ cb) {
    extern __shared__ float sm[];      // [xs0|xs1|es0|es1], TILE floats each
    const int tid = threadIdx.x;
    const int tx  = tid & 15;
    const int ty  = tid >> 4;
    const int rowbase = blockIdx.x * BM;
    const int kbase   = blockIdx.y * BN;
    const float4* x4  = reinterpret_cast<const float4*>(x);
    const float4* cb4 = reinterpret_cast<const float4*>(cb);

    const int r8  = tid >> 3;          // 0..31 base row for loads (i>>3 with it offset)
    const int d4l = tid & 7;           // float4 index within chunk

    float acc[8][8];
#pragma unroll
    for (int i = 0; i < 8; i++)
#pragma unroll
        for (int j = 0; j < 8; j++) acc[i][j] = 0.0f;

    float4 px[4], pe[4];

    // prologue: load chunk 0
#pragma unroll
    for (int it = 0; it < 4; it++) {
        int r = it * 32 + r8;
        px[it] = x4[(size_t)(rowbase + r) * 64 + d4l];
        pe[it] = cb4[(size_t)(kbase + r) * 64 + d4l];
    }
    {
        float* xs = sm;
        float* es = sm + 2 * TILE;
#pragma unroll
        for (int it = 0; it < 4; it++) {
            int r = it * 32 + r8;
            *reinterpret_cast<float4*>(&xs[r * XSTR + d4l * 4]) = px[it];
            *reinterpret_cast<float4*>(&es[r * XSTR + d4l * 4]) = pe[it];
        }
    }
    __syncthreads();

#pragma unroll 1
    for (int t = 0; t < DIM / BK; t++) {           // 8 chunks
        if (t < 7) {
#pragma unroll
            for (int it = 0; it < 4; it++) {
                int r = it * 32 + r8;
                px[it] = x4[(size_t)(rowbase + r) * 64 + (t + 1) * 8 + d4l];
                pe[it] = cb4[(size_t)(kbase + r) * 64 + (t + 1) * 8 + d4l];
            }
        }
        {
            const float* xs = sm + (t & 1) * TILE;
            const float* es = sm + 2 * TILE + (t & 1) * TILE;
#pragma unroll
            for (int d4 = 0; d4 < 8; d4++) {
                float4 xv[8], ev[8];
#pragma unroll
                for (int i = 0; i < 8; i++)
                    xv[i] = *reinterpret_cast<const float4*>(&xs[(i * 16 + ty) * XSTR + d4 * 4]);
#pragma unroll
                for (int j = 0; j < 8; j++)
                    ev[j] = *reinterpret_cast<const float4*>(&es[(j * 16 + tx) * XSTR + d4 * 4]);
#pragma unroll
                for (int i = 0; i < 8; i++)
#pragma unroll
                    for (int j = 0; j < 8; j++) {
                        acc[i][j] = __fmaf_rn(xv[i].x, ev[j].x, acc[i][j]);
                        acc[i][j] = __fmaf_rn(xv[i].y, ev[j].y, acc[i][j]);
                        acc[i][j] = __fmaf_rn(xv[i].z, ev[j].z, acc[i][j]);
                        acc[i][j] = __fmaf_rn(xv[i].w, ev[j].w, acc[i][j]);
                    }
            }
        }
        if (t < 7) {
            float* xs = sm + ((t + 1) & 1) * TILE;
            float* es = sm + 2 * TILE + ((t + 1) & 1) * TILE;
#pragma unroll
            for (int it = 0; it < 4; it++) {
                int r = it * 32 + r8;
                *reinterpret_cast<float4*>(&xs[r * XSTR + d4l * 4]) = px[it];
                *reinterpret_cast<float4*>(&es[r * XSTR + d4l * 4]) = pe[it];
            }
            __syncthreads();
        }
    }

    // Epilogue: distances + lexicographic argmin (first-index tie-break).
    float rr[8];
#pragma unroll
    for (int i = 0; i < 8; i++) rr[i] = g_rown[rowbase + i * 16 + ty];
    unsigned long long bk[8];
#pragma unroll
    for (int i = 0; i < 8; i++) bk[i] = ~0ull;
#pragma unroll
    for (int j = 0; j < 8; j++) {
        int   kg = kbase + j * 16 + tx;
        float c  = g_coden[kg];
#pragma unroll
        for (int i = 0; i < 8; i++) {
            float dist = __fsub_rn(__fadd_rn(rr[i], c), 2.0f * acc[i][j]);
            unsigned long long key =
                ((unsigned long long)__float_as_uint(dist) << 32) | (unsigned)kg;
            if (key < bk[i]) bk[i] = key;
        }
    }
    // reduce across the 16 tx lanes sharing each row (lane = (ty&1)*16+tx)
#pragma unroll
    for (int i = 0; i < 8; i++) {
        unsigned long long k = bk[i];
#pragma unroll
        for (int off = 8; off >= 1; off >>= 1) {
            unsigned long long o = __shfl_xor_sync(0xffffffffu, k, off);
            if (o < k) k = o;
        }
        if (tx == 0) atomicMin(&g_key[rowbase + i * 16 + ty], k);
    }
}

// ---------------------------------------------------------------------------
__global__ void k_gather(const float* __restrict__ x, const float* __restrict__ cb,
                         float* __restrict__ out, int out_size) {
    double ls = 0.0;
    const int total = NTOK * DIM;
    for (int e = blockIdx.x * 256 + threadIdx.x; e < total; e += 1024 * 256) {
        int n = e >> 8, d = e & 255;
        int idx = (int)(unsigned)(g_key[n] & 0xffffffffull);
        float q  = __ldg(&cb[idx * DIM + d]);
        float xv = x[e];
        float diff = __fsub_rn(q, xv);
        if (e < out_size) out[e] = __fadd_rn(xv, diff);
        ls += (double)__fmul_rn(diff, diff);
    }
#pragma unroll
    for (int off = 16; off >= 1; off >>= 1)
        ls += __shfl_xor_sync(0xffffffffu, ls, off);
    __shared__ double ws[8];
    if ((threadIdx.x & 31) == 0) ws[threadIdx.x >> 5] = ls;
    __syncthreads();
    if (threadIdx.x == 0) {
        double t = 0.0;
        for (int w = 0; w < 8; w++) t += ws[w];
        g_partial[blockIdx.x] = t;
    }
}

// ---------------------------------------------------------------------------
__global__ void k_finalize(float* __restrict__ out, int out_size) {
    if (blockIdx.x < 64) {
        int n = blockIdx.x * 256 + threadIdx.x;
        int pos = NTOK * DIM + n;
        if (pos < out_size)
            out[pos] = (float)(unsigned)(g_key[n] & 0xffffffffull);
    } else if (threadIdx.x == 0) {
        double s = 0.0;
        for (int b = 0; b < 1024; b++) s += g_partial[b];
        int pos = NTOK * DIM + NTOK;
        if (pos < out_size)
            out[pos] = 0.25f * (float)(s / (double)(NTOK * DIM));
    }
}

// ---------------------------------------------------------------------------
extern "C" void kernel_launch(void* const* d_in, const int* in_sizes, int n_in,
                              void* d_out, int out_size) {
    const float* x  = (const float*)d_in[0];
    const float* cb = (const float*)d_in[1];
    if (n_in >= 2 && in_sizes[0] == NCODES * DIM) {
        cb = (const float*)d_in[0];
        x  = (const float*)d_in[1];
    }
    float* out = (float*)d_out;

    const int smem = 4 * TILE * (int)sizeof(float);   // 73728 B
    cudaFuncSetAttribute(k_main, cudaFuncAttributeMaxDynamicSharedMemorySize, smem);

    k_init<<<(NTOK + 255) / 256, 256>>>();
    k_norm<<<NTOK / 8, 256>>>(x, NTOK, 0);
    k_norm<<<NCODES / 8, 256>>>(cb, NCODES, 1);
    k_main<<<dim3(NTOK / BM, NCODES / BN), 256, smem>>>(x, cb);
    k_gather<<<1024, 256>>>(x, cb, out, out_size);
    k_finalize<<<65, 256>>>(out, out_size);
}